// round 1
// baseline (speedup 1.0000x reference)
#include <cuda_runtime.h>
#include <cuda_bf16.h>
#include <math.h>

#define BB    8
#define CC    64
#define HEADS 4
#define CH    16
#define HH    256
#define WW    256
#define HW    (HH*WW)
#define EPS   1e-12f

// ---------------- static device scratch (no allocs allowed) ----------------
__device__ float g_q [BB*CC*HW];   // 134 MB : q  (reused as resblock scratch)
__device__ float g_k [BB*CC*HW];   // 134 MB : k  (reused as resblock scratch)
__device__ float g_v [BB*CC*HW];   // 134 MB : v
__device__ float g_t0[BB*CC*HW];   // 134 MB : attention output / resblock input
__device__ float g_gram[BB*HEADS*CH*CH];
__device__ float g_qn[BB*CC];
__device__ float g_kn[BB*CC];
__device__ float g_attn[BB*HEADS*CH*CH];

// ---------------- zero the small accumulators (graph replays!) -------------
__global__ void k_zero_small() {
    int tid = threadIdx.x;
    for (int i = tid; i < BB*HEADS*CH*CH; i += 1024) { g_gram[i] = 0.f; g_attn[i] = 0.f; }
    for (int i = tid; i < BB*CC; i += 1024)          { g_qn[i] = 0.f;  g_kn[i] = 0.f; }
}

// ---------------- fused q,k,v 1x1 convs ------------------------------------
// one thread = one pixel; weights transposed [in][out] in smem, float4 loads.
__device__ __forceinline__ void conv1x1_px(const float* src, const float* swp,
                                           const float* bglob, float* dst) {
    float acc[64];
#pragma unroll
    for (int oc = 0; oc < 64; oc++) acc[oc] = __ldg(&bglob[oc]);
#pragma unroll 2
    for (int i = 0; i < 64; i++) {
        float xi = src[i*HW];
        const float4* w4 = reinterpret_cast<const float4*>(swp + i*64);
#pragma unroll
        for (int o4 = 0; o4 < 16; o4++) {
            float4 w = w4[o4];
            acc[o4*4+0] += w.x*xi; acc[o4*4+1] += w.y*xi;
            acc[o4*4+2] += w.z*xi; acc[o4*4+3] += w.w*xi;
        }
    }
#pragma unroll
    for (int oc = 0; oc < 64; oc++) dst[oc*HW] = acc[oc];
}

__global__ void k_qkv(const float* __restrict__ x,  const float* __restrict__ y,
                      const float* __restrict__ qw, const float* __restrict__ qb,
                      const float* __restrict__ kw, const float* __restrict__ kb,
                      const float* __restrict__ vw, const float* __restrict__ vb) {
    __shared__ float sw[3*64*64];               // 48 KB exactly (transposed [i][oc])
    int tid = threadIdx.x;
    for (int idx = tid; idx < 64*64; idx += 256) {
        int oc = idx >> 6, i = idx & 63;
        sw[0*4096 + i*64 + oc] = qw[idx];
        sw[1*4096 + i*64 + oc] = kw[idx];
        sw[2*4096 + i*64 + oc] = vw[idx];
    }
    __syncthreads();
    int b  = blockIdx.y;
    int px = blockIdx.x*256 + tid;
    const float* xb = x + (size_t)b*CC*HW + px;
    const float* yb = y + (size_t)b*CC*HW + px;
    float* qo = g_q + (size_t)b*CC*HW + px;
    float* ko = g_k + (size_t)b*CC*HW + px;
    float* vo = g_v + (size_t)b*CC*HW + px;
    conv1x1_px(xb, sw + 0*4096, qb, qo);
    conv1x1_px(yb, sw + 1*4096, kb, ko);
    conv1x1_px(yb, sw + 2*4096, vb, vo);
}

// ---------------- Gram matrices + row norms (fused reduction) --------------
// grid = (32 n-chunks, B*HEADS); block = 256 = (c,d) 16x16. Each block reduces
// a 2048-wide n slab in 64-wide smem tiles, atomics merge 32 partials.
__global__ void k_gram() {
    __shared__ float qs[16*65];
    __shared__ float ks[16*65];
    int tid = threadIdx.x;
    int c = tid & 15, d = tid >> 4;
    int bh = blockIdx.y, b = bh >> 2, h = bh & 3;
    const float* qp = g_q + ((size_t)b*CC + h*CH)*HW;
    const float* kp = g_k + ((size_t)b*CC + h*CH)*HW;
    float acc = 0.f, nacc = 0.f;
    for (int t = 0; t < 32; t++) {
        int n0 = blockIdx.x*2048 + t*64;
        for (int idx = tid; idx < 1024; idx += 256) {
            int r = idx >> 6, j = idx & 63;
            qs[r*65 + j] = qp[(size_t)r*HW + n0 + j];
            ks[r*65 + j] = kp[(size_t)r*HW + n0 + j];
        }
        __syncthreads();
#pragma unroll 8
        for (int j = 0; j < 64; j++) acc += qs[c*65 + j] * ks[d*65 + j];
        if (d == 0) {
#pragma unroll 8
            for (int j = 0; j < 64; j++) { float v = qs[c*65 + j]; nacc += v*v; }
        } else if (d == 1) {
#pragma unroll 8
            for (int j = 0; j < 64; j++) { float v = ks[c*65 + j]; nacc += v*v; }
        }
        __syncthreads();
    }
    atomicAdd(&g_gram[bh*256 + c*16 + d], acc);
    if (d == 0) atomicAdd(&g_qn[b*CC + h*CH + c], nacc);
    if (d == 1) atomicAdd(&g_kn[b*CC + h*CH + c], nacc);
}

// ---------------- softmax over d (tiny) ------------------------------------
__global__ void k_softmax() {
    int tid = threadIdx.x;              // 512 = 32 bh * 16 rows
    int bh = tid >> 4, c = tid & 15;
    int b = bh >> 2, h = bh & 3;
    float nq = fmaxf(sqrtf(g_qn[b*CC + h*CH + c]), EPS);
    float l[16], m = -1e30f;
#pragma unroll
    for (int d = 0; d < 16; d++) {
        float nk = fmaxf(sqrtf(g_kn[b*CC + h*CH + d]), EPS);
        l[d] = g_gram[bh*256 + c*16 + d] / (nq * nk);
        m = fmaxf(m, l[d]);
    }
    float s = 0.f;
#pragma unroll
    for (int d = 0; d < 16; d++) { l[d] = expf(l[d] - m); s += l[d]; }
    float inv = 1.f / s;
#pragma unroll
    for (int d = 0; d < 16; d++) g_attn[bh*256 + c*16 + d] = l[d] * inv;
}

// ---------------- out = attn @ v -------------------------------------------
__global__ void k_apply() {
    __shared__ float sa[HEADS*CH*CH];   // 1024 floats
    int tid = threadIdx.x;
    int b = blockIdx.y;
    for (int i = tid; i < 1024; i += 256) sa[i] = g_attn[b*1024 + i];
    __syncthreads();
    int px = blockIdx.x*256 + tid;
    const float* vb = g_v  + (size_t)b*CC*HW + px;
    float*       ob = g_t0 + (size_t)b*CC*HW + px;
#pragma unroll
    for (int h = 0; h < 4; h++) {
        float vr[16];
#pragma unroll
        for (int d = 0; d < 16; d++) vr[d] = vb[(size_t)(h*CH + d)*HW];
#pragma unroll
        for (int c = 0; c < 16; c++) {
            const float4* a4 = reinterpret_cast<const float4*>(sa + h*256 + c*16);
            float s = 0.f;
#pragma unroll
            for (int d4 = 0; d4 < 4; d4++) {
                float4 a = a4[d4];
                s += a.x*vr[d4*4+0] + a.y*vr[d4*4+1] + a.z*vr[d4*4+2] + a.w*vr[d4*4+3];
            }
            ob[(size_t)(h*CH + c)*HW] = s;
        }
    }
}

// ---------------- 3x3 conv, 64->64, pad 1 ----------------------------------
// block = 128 thr (32x4); tile 32x8 px, 16 out-ch per block; thread owns
// 2 pixels x 16 oc. Weights smem-transposed [ic][tap][oc] for float4 broadcast.
#define TW   32
#define TH   8
#define ICC  16
__global__ void __launch_bounds__(128) k_conv3(
        const float* __restrict__ in, const float* __restrict__ w,
        const float* __restrict__ bias, const float* __restrict__ skip,
        const float* __restrict__ skip2, float* __restrict__ out, int do_relu) {
    __shared__ float sIn[ICC*(TH+2)*(TW+2)];
    __shared__ float sW [ICC*9*16];
    int tid = threadIdx.x;
    int tx = tid & 31, tyq = tid >> 5;            // tyq in [0,4)
    int bz = blockIdx.z, b = bz >> 2, ocg = bz & 3;
    int gx0 = blockIdx.x*TW, gy0 = blockIdx.y*TH;
    const float* inb = in + (size_t)b*CC*HW;
    float acc0[16], acc1[16];
#pragma unroll
    for (int o = 0; o < 16; o++) { acc0[o] = 0.f; acc1[o] = 0.f; }

    for (int icc = 0; icc < 64; icc += ICC) {
        // input tile (zero-padded borders)
        for (int idx = tid; idx < ICC*(TH+2)*(TW+2); idx += 128) {
            int ic = idx / ((TH+2)*(TW+2));
            int r  = idx % ((TH+2)*(TW+2));
            int yy = r / (TW+2), xx = r % (TW+2);
            int gy = gy0 + yy - 1, gx = gx0 + xx - 1;
            float vv = 0.f;
            if (gy >= 0 && gy < HH && gx >= 0 && gx < WW)
                vv = inb[(size_t)(icc+ic)*HW + gy*WW + gx];
            sIn[idx] = vv;
        }
        // weight slab: sW[ic][tap][oc]
        for (int idx = tid; idx < ICC*9*16; idx += 128) {
            int oc = idx & 15; int rem = idx >> 4;
            int tap = rem % 9, ic = rem / 9;
            sW[ic*144 + tap*16 + oc] = w[(size_t)(ocg*16+oc)*576 + (icc+ic)*9 + tap];
        }
        __syncthreads();

        for (int ic = 0; ic < ICC; ic++) {
            float x0[9], x1[9];
#pragma unroll
            for (int ky = 0; ky < 3; ky++)
#pragma unroll
                for (int kx = 0; kx < 3; kx++) {
                    x0[ky*3+kx] = sIn[ic*((TH+2)*(TW+2)) + (tyq+ky)  *(TW+2) + tx+kx];
                    x1[ky*3+kx] = sIn[ic*((TH+2)*(TW+2)) + (tyq+4+ky)*(TW+2) + tx+kx];
                }
#pragma unroll
            for (int tap = 0; tap < 9; tap++) {
                const float4* w4 = reinterpret_cast<const float4*>(&sW[ic*144 + tap*16]);
                float a0 = x0[tap], a1 = x1[tap];
#pragma unroll
                for (int o4 = 0; o4 < 4; o4++) {
                    float4 wv = w4[o4];
                    acc0[o4*4+0] += wv.x*a0; acc1[o4*4+0] += wv.x*a1;
                    acc0[o4*4+1] += wv.y*a0; acc1[o4*4+1] += wv.y*a1;
                    acc0[o4*4+2] += wv.z*a0; acc1[o4*4+2] += wv.z*a1;
                    acc0[o4*4+3] += wv.w*a0; acc1[o4*4+3] += wv.w*a1;
                }
            }
        }
        __syncthreads();
    }
    // epilogue: bias, relu, skips, store
#pragma unroll
    for (int r2 = 0; r2 < 2; r2++) {
        int gy = gy0 + tyq + r2*4;
#pragma unroll
        for (int o = 0; o < 16; o++) {
            int oc = ocg*16 + o;
            size_t idx = (size_t)b*CC*HW + (size_t)oc*HW + (size_t)gy*WW + gx0 + tx;
            float v = (r2 ? acc1[o] : acc0[o]) + __ldg(&bias[oc]);
            if (do_relu) v = fmaxf(v, 0.f);
            if (skip)  v += skip[idx];
            if (skip2) v += skip2[idx];
            out[idx] = v;
        }
    }
}

// ---------------- launcher ---------------------------------------------------
extern "C" void kernel_launch(void* const* d_in, const int* in_sizes, int n_in,
                              void* d_out, int out_size) {
    const float* x    = (const float*)d_in[0];
    const float* y    = (const float*)d_in[1];
    const float* qw   = (const float*)d_in[2];
    const float* qb   = (const float*)d_in[3];
    const float* kw   = (const float*)d_in[4];
    const float* kb   = (const float*)d_in[5];
    const float* vw   = (const float*)d_in[6];
    const float* vb   = (const float*)d_in[7];
    const float* r1w1 = (const float*)d_in[8];
    const float* r1b1 = (const float*)d_in[9];
    const float* r1w2 = (const float*)d_in[10];
    const float* r1b2 = (const float*)d_in[11];
    const float* r2w1 = (const float*)d_in[12];
    const float* r2b1 = (const float*)d_in[13];
    const float* r2w2 = (const float*)d_in[14];
    const float* r2b2 = (const float*)d_in[15];
    float* outp = (float*)d_out;

    float *pq, *pk, *pt0;
    cudaGetSymbolAddress((void**)&pq,  g_q);
    cudaGetSymbolAddress((void**)&pk,  g_k);
    cudaGetSymbolAddress((void**)&pt0, g_t0);

    k_zero_small<<<1, 1024>>>();
    k_qkv <<<dim3(HW/256, BB), 256>>>(x, y, qw, qb, kw, kb, vw, vb);
    k_gram<<<dim3(32, BB*HEADS), 256>>>();
    k_softmax<<<1, 512>>>();
    k_apply<<<dim3(HW/256, BB), 256>>>();

    dim3 cgrid(WW/TW, HH/TH, BB*4);
    // resblock 1: t0 -> q (relu conv1), q -> k (conv2 + t0 skip)
    k_conv3<<<cgrid, 128>>>(pt0, r1w1, r1b1, nullptr, nullptr, pq, 1);
    k_conv3<<<cgrid, 128>>>(pq,  r1w2, r1b2, pt0,     nullptr, pk, 0);
    // resblock 2: k -> q (relu conv1), q -> d_out (conv2 + k skip + y)
    k_conv3<<<cgrid, 128>>>(pk,  r2w1, r2b1, nullptr, nullptr, pq, 1);
    k_conv3<<<cgrid, 128>>>(pq,  r2w2, r2b2, pk,      y,       outp, 0);
}